// round 7
// baseline (speedup 1.0000x reference)
#include <cuda_runtime.h>
#include <cuda_bf16.h>

// Problem constants
#define BN 1024   // batch
#define TT 512    // seq len
#define EE 64     // embedding
#define H1N 50    // layer-1 hidden
#define G1N 200   // 4*H1
#define HS 52     // padded row stride (floats) for h scratch / smem rows
#define NPAIR 26  // 52/2 j-pairs (j=50,51 zero-padded)

// Scratch (static __device__ globals -- allocation-free per harness rules)
__device__ float g_hf[BN * TT * HS];     // layer1 fwd h, [b][t][j], stride HS
__device__ float g_hb[BN * TT * HS];     // layer1 bwd-dir h at its own step s
__device__ float g_xg1[2 * BN * G1N];    // layer1 input contribution per dir
__device__ float g_xg2f[BN * TT * 4];    // layer2 fwd input gates
__device__ float g_xg2b[BN * TT * 4];    // layer2 bwd input gates
__device__ float g_h2b[BN * TT];         // layer2 bwd output (time-indexed)
__device__ int   g_clf[BN];              // fwd convergence clamp per batch
__device__ int   g_clb[BN];              // bwd convergence clamp per batch

__device__ __forceinline__ float sigx(float x) {
    return __fdividef(1.0f, 1.0f + __expf(-x));
}
__device__ __forceinline__ float tanhx(float x) {
    return __fdividef(2.0f, 1.0f + __expf(-2.0f * x)) - 1.0f;
}

// packed f32x2 helpers (FFMA2 only reachable via PTX fma.rn.f32x2 on sm_103a)
__device__ __forceinline__ unsigned long long pk2(float lo, float hi) {
    unsigned long long r;
    asm("mov.b64 %0, {%1, %2};" : "=l"(r) : "f"(lo), "f"(hi));
    return r;
}
__device__ __forceinline__ float2 upk2(unsigned long long v) {
    float2 r;
    asm("mov.b64 {%0, %1}, %2;" : "=f"(r.x), "=f"(r.y) : "l"(v));
    return r;
}
__device__ __forceinline__ void fma2(unsigned long long& d,
                                     unsigned long long a, unsigned long long b) {
    asm("fma.rn.f32x2 %0, %1, %2, %0;" : "+l"(d) : "l"(a), "l"(b));
}

// ---------------------------------------------------------------------------
// Kernel A: xg1[dir][b][g] = (b_ih+b_hh)[g] + sum_e W_ih[g][e] * x[b][e]
// Input is constant in time -> computed ONCE per (b, dir).
// ---------------------------------------------------------------------------
__global__ void __launch_bounds__(256) xg1_kernel(
    const float* __restrict__ x,
    const float* __restrict__ Wif, const float* __restrict__ bif, const float* __restrict__ bhf,
    const float* __restrict__ Wib, const float* __restrict__ bib, const float* __restrict__ bhb)
{
    __shared__ __align__(16) float sx[EE];
    int b = blockIdx.x;
    int tid = threadIdx.x;
    if (tid < EE) sx[tid] = x[b * EE + tid];
    __syncthreads();

    for (int o = tid; o < 2 * G1N; o += 256) {
        int dir = o / G1N;
        int g = o - dir * G1N;
        const float* W = dir ? Wib : Wif;
        float acc = dir ? (bib[g] + bhb[g]) : (bif[g] + bhf[g]);
        const float4* wr = (const float4*)&W[g * EE];
        #pragma unroll
        for (int e = 0; e < EE / 4; e++) {
            float4 w = wr[e];
            float4 xv = *(const float4*)&sx[4 * e];
            acc += w.x * xv.x + w.y * xv.y + w.z * xv.z + w.w * xv.w;
        }
        g_xg1[dir * BN * G1N + b * G1N + g] = acc;
    }
}

// ---------------------------------------------------------------------------
// Kernel B: layer-1 recurrence, quad-gate layout.
// One CTA = 4 batch lanes of one direction. Thread tid = u*4 + gt
// (u = hidden unit 0..49, gt = gate type 0:i 1:f 2:g 3:o).
// Each thread holds W_hh row (gate gt*50+u) j-pair-packed in 26 f32x2 regs,
// computes its gate for 4 lanes, exchanges gates within the quad via
// __shfl_sync (same warp), and gt==0 does the c/h update. Double-buffered
// sh_h -> ONE barrier per step (the __syncthreads_and, which also carries
// the bitwise fixed-point early-exit vote).
// ---------------------------------------------------------------------------
__global__ void __launch_bounds__(224, 3) lstm1_kernel(
    const float* __restrict__ Whhf, const float* __restrict__ Whhb)
{
    int grp = blockIdx.x;      // 0..255  (batch group of 4)
    int dir = blockIdx.y;      // 0..1
    int b0 = grp * 4;
    const float* Whh = dir ? Whhb : Whhf;
    float* hout = dir ? g_hb : g_hf;
    int* clampp = dir ? g_clb : g_clf;

    __shared__ __align__(16) float sh_h[2][4 * HS];   // double-buffered [lane][j]

    int tid = threadIdx.x;
    int u = tid >> 2;
    int gt = tid & 3;
    bool active = (tid < G1N);
    bool is_tanh = (gt == 2);
    bool is_upd = (gt == 0);
    unsigned mask = (tid < 192) ? 0xFFFFFFFFu : 0xFFu;  // warp 6: lanes 0..7 active
    int qb = (tid & 31) & ~3;                           // quad base lane

    unsigned long long W2[NPAIR];
    float xg[4];
    if (active) {
        int grow = gt * H1N + u;   // gate row in PyTorch order
        #pragma unroll
        for (int p = 0; p < NPAIR; p++) {
            float w0 = (2 * p     < H1N) ? Whh[grow * H1N + 2 * p]     : 0.f;
            float w1 = (2 * p + 1 < H1N) ? Whh[grow * H1N + 2 * p + 1] : 0.f;
            W2[p] = pk2(w0, w1);
        }
        const float* xb = g_xg1 + dir * BN * G1N;
        #pragma unroll
        for (int l = 0; l < 4; l++) xg[l] = xb[(b0 + l) * G1N + grow];
    }
    for (int i = tid; i < 2 * 4 * HS; i += 224) ((float*)sh_h)[i] = 0.f;

    float c_st[4] = {0.f, 0.f, 0.f, 0.f};
    float h_st[4] = {0.f, 0.f, 0.f, 0.f};
    __syncthreads();

    int tconv = TT - 1;
    for (int t = 0; t < TT; t++) {
        int pred = 1;
        if (active) {
            const float* hb = sh_h[t & 1];
            float* hw = sh_h[(t + 1) & 1];
            float a[4];
            #pragma unroll
            for (int l = 0; l < 4; l++) {
                unsigned long long acc = pk2(xg[l], 0.f);
                #pragma unroll
                for (int c = 0; c < HS / 4; c++) {     // 13 chunks of 4 j
                    ulonglong2 hv = *(const ulonglong2*)&hb[l * HS + 4 * c];
                    fma2(acc, W2[2 * c], hv.x);
                    fma2(acc, W2[2 * c + 1], hv.y);
                }
                float2 uu = upk2(acc);
                float s = uu.x + uu.y;
                a[l] = is_tanh ? tanhx(s) : sigx(s);
            }
            #pragma unroll
            for (int l = 0; l < 4; l++) {
                float xi = __shfl_sync(mask, a[l], qb + 0);
                float xf = __shfl_sync(mask, a[l], qb + 1);
                float xgg = __shfl_sync(mask, a[l], qb + 2);
                float xo = __shfl_sync(mask, a[l], qb + 3);
                if (is_upd) {
                    float cn = xf * c_st[l] + xi * xgg;
                    float hn = xo * tanhx(cn);
                    pred &= (__float_as_int(cn) == __float_as_int(c_st[l])) &
                            (__float_as_int(hn) == __float_as_int(h_st[l]));
                    c_st[l] = cn; h_st[l] = hn;
                    hw[l * HS + u] = hn;
                    hout[((b0 + l) * TT + t) * HS + u] = hn;
                }
            }
        }
        int conv = __syncthreads_and(pred);
        if (conv) { tconv = t; break; }   // state bitwise-repeated -> exact from here on
    }
    if (tid < 4) clampp[b0 + tid] = tconv;
}

// ---------------------------------------------------------------------------
// Kernel C: layer-2 input gates. One thread per (b, t).
//   h1[b][t] = [hf[b][t], hb_dir[b][511-t]]   (clamped by convergence index)
//   xg2f[b][t]      = b2f + W_ih2f . h1[b][t]
//   xg2b[b][511-t]  = b2b + W_ih2b . h1[b][t]
// ---------------------------------------------------------------------------
__global__ void __launch_bounds__(256) xg2_kernel(
    const float* __restrict__ Wf, const float* __restrict__ Wb,
    const float* __restrict__ bif, const float* __restrict__ bhf,
    const float* __restrict__ bib, const float* __restrict__ bhb)
{
    __shared__ __align__(16) float sWf[4 * 104];
    __shared__ __align__(16) float sWb[4 * 104];
    __shared__ float sbf[4], sbb[4];
    int tid = threadIdx.x;
    for (int i = tid; i < 400; i += 256) {
        int g = i / 100, j = i - g * 100;
        int off = g * 104 + j + (j >= 50 ? 2 : 0);  // hb half padded to 16B align
        sWf[off] = Wf[i];
        sWb[off] = Wb[i];
    }
    if (tid < 4) { sbf[tid] = bif[tid] + bhf[tid]; sbb[tid] = bib[tid] + bhb[tid]; }
    __syncthreads();

    int idx = blockIdx.x * 256 + tid;
    int b = idx >> 9;
    int t = idx & (TT - 1);
    int tc = min(t, g_clf[b]);
    int sc = min(TT - 1 - t, g_clb[b]);
    const float* hfr = &g_hf[(b * TT + tc) * HS];
    const float* hbr = &g_hb[(b * TT + sc) * HS];

    float accf[4], accb[4];
    #pragma unroll
    for (int g = 0; g < 4; g++) { accf[g] = sbf[g]; accb[g] = sbb[g]; }

    // forward-h half (weight cols 0..49)
    #pragma unroll
    for (int k = 0; k < 12; k++) {
        float4 hv = *(const float4*)&hfr[4 * k];
        #pragma unroll
        for (int g = 0; g < 4; g++) {
            float4 wf = *(const float4*)&sWf[g * 104 + 4 * k];
            float4 wb = *(const float4*)&sWb[g * 104 + 4 * k];
            accf[g] += wf.x * hv.x + wf.y * hv.y + wf.z * hv.z + wf.w * hv.w;
            accb[g] += wb.x * hv.x + wb.y * hv.y + wb.z * hv.z + wb.w * hv.w;
        }
    }
    {
        float h48 = hfr[48], h49 = hfr[49];
        #pragma unroll
        for (int g = 0; g < 4; g++) {
            accf[g] += sWf[g * 104 + 48] * h48 + sWf[g * 104 + 49] * h49;
            accb[g] += sWb[g * 104 + 48] * h48 + sWb[g * 104 + 49] * h49;
        }
    }
    // backward-h half (weight cols 50..99, stored at smem offset 52..101)
    #pragma unroll
    for (int k = 0; k < 12; k++) {
        float4 hv = *(const float4*)&hbr[4 * k];
        #pragma unroll
        for (int g = 0; g < 4; g++) {
            float4 wf = *(const float4*)&sWf[g * 104 + 52 + 4 * k];
            float4 wb = *(const float4*)&sWb[g * 104 + 52 + 4 * k];
            accf[g] += wf.x * hv.x + wf.y * hv.y + wf.z * hv.z + wf.w * hv.w;
            accb[g] += wb.x * hv.x + wb.y * hv.y + wb.z * hv.z + wb.w * hv.w;
        }
    }
    {
        float h48 = hbr[48], h49 = hbr[49];
        #pragma unroll
        for (int g = 0; g < 4; g++) {
            accf[g] += sWf[g * 104 + 100] * h48 + sWf[g * 104 + 101] * h49;
            accb[g] += sWb[g * 104 + 100] * h48 + sWb[g * 104 + 101] * h49;
        }
    }

    *(float4*)&g_xg2f[(b * TT + t) * 4] = make_float4(accf[0], accf[1], accf[2], accf[3]);
    *(float4*)&g_xg2b[(b * TT + (TT - 1 - t)) * 4] = make_float4(accb[0], accb[1], accb[2], accb[3]);
}

// ---------------------------------------------------------------------------
// Kernel D: layer-2 recurrence, quad-gate layout. H2=1 -> scalar state.
// 4 threads per (b, dir) chain, one gate each; quad shuffle exchanges the
// activated gates; all 4 threads redundantly track (c, h) (bitwise identical)
// so h is available for the next step without a broadcast. 8192 threads over
// 256 CTAs -> spread over the whole chip (old version used 8 SMs and was
// latency-chain-bound at ~850 cyc/step).
// ---------------------------------------------------------------------------
__global__ void __launch_bounds__(32) lstm2_kernel(
    const float* __restrict__ Whhf, const float* __restrict__ Whhb,
    float* __restrict__ out)
{
    int gid = blockIdx.x * 32 + threadIdx.x;   // 0..8191
    int chain = gid >> 2;                       // 0..2047
    int gt = gid & 3;
    int b = chain & (BN - 1);
    bool bwd = (chain >= BN);
    const float* Whh = bwd ? Whhb : Whhf;
    float w = Whh[gt];
    const float* pre = (bwd ? g_xg2b : g_xg2f) + b * TT * 4 + gt;
    bool is_tanh = (gt == 2);
    bool is_st = (gt == 0);
    int qb = (threadIdx.x & 31) & ~3;

    float h = 0.f, c = 0.f;
    for (int t = 0; t < TT; t++) {
        float a = pre[t * 4] + w * h;
        a = is_tanh ? tanhx(a) : sigx(a);
        float xi = __shfl_sync(0xFFFFFFFFu, a, qb + 0);
        float xf = __shfl_sync(0xFFFFFFFFu, a, qb + 1);
        float xgg = __shfl_sync(0xFFFFFFFFu, a, qb + 2);
        float xo = __shfl_sync(0xFFFFFFFFu, a, qb + 3);
        c = xf * c + xi * xgg;
        h = xo * tanhx(c);
        if (is_st) {
            if (!bwd) out[b * TT + t] = h;
            else      g_h2b[b * TT + (TT - 1 - t)] = h;
        }
    }
}

// ---------------------------------------------------------------------------
// Kernel E: out += h2b (final channel sum)
// ---------------------------------------------------------------------------
__global__ void __launch_bounds__(256) addout_kernel(float* __restrict__ out)
{
    int i = blockIdx.x * 256 + threadIdx.x;   // 0..131071 float4s
    float4* o = (float4*)out;
    const float4* s = (const float4*)g_h2b;
    float4 a = o[i], bv = s[i];
    a.x += bv.x; a.y += bv.y; a.z += bv.z; a.w += bv.w;
    o[i] = a;
}

// ---------------------------------------------------------------------------
extern "C" void kernel_launch(void* const* d_in, const int* in_sizes, int n_in,
                              void* d_out, int out_size)
{
    const float* x    = (const float*)d_in[0];
    const float* Wif1 = (const float*)d_in[1];
    const float* Whf1 = (const float*)d_in[2];
    const float* bif1 = (const float*)d_in[3];
    const float* bhf1 = (const float*)d_in[4];
    const float* Wib1 = (const float*)d_in[5];
    const float* Whb1 = (const float*)d_in[6];
    const float* bib1 = (const float*)d_in[7];
    const float* bhb1 = (const float*)d_in[8];
    const float* Wif2 = (const float*)d_in[9];
    const float* Whf2 = (const float*)d_in[10];
    const float* bif2 = (const float*)d_in[11];
    const float* bhf2 = (const float*)d_in[12];
    const float* Wib2 = (const float*)d_in[13];
    const float* Whb2 = (const float*)d_in[14];
    const float* bib2 = (const float*)d_in[15];
    const float* bhb2 = (const float*)d_in[16];
    float* out = (float*)d_out;

    xg1_kernel<<<BN, 256>>>(x, Wif1, bif1, bhf1, Wib1, bib1, bhb1);
    dim3 gB(BN / 4, 2);
    lstm1_kernel<<<gB, 224>>>(Whf1, Whb1);
    xg2_kernel<<<(BN * TT) / 256, 256>>>(Wif2, Wib2, bif2, bhf2, bib2, bhb2);
    lstm2_kernel<<<256, 32>>>(Whf2, Whb2, out);
    addout_kernel<<<(BN * TT) / 1024, 256>>>(out);
}

// round 14
// speedup vs baseline: 1.8741x; 1.8741x over previous
#include <cuda_runtime.h>
#include <cuda_bf16.h>

// Problem constants
#define BN 1024   // batch
#define TT 512    // seq len
#define EE 64     // embedding
#define H1N 50    // layer-1 hidden
#define G1N 200   // 4*H1
#define HS 52     // padded row stride for h1 scratch (16B aligned rows)

// Scratch (static __device__ globals -- allocation-free per harness rules)
__device__ float g_hf[BN * TT * HS];     // layer1 fwd h, [b][t][j], stride HS
__device__ float g_hb[BN * TT * HS];     // layer1 bwd-dir h at its own step s
__device__ float g_xg1[2 * BN * G1N];    // layer1 input contribution per dir
__device__ float g_xg2f[BN * TT * 4];    // layer2 fwd input gates
__device__ float g_xg2b[BN * TT * 4];    // layer2 bwd input gates
__device__ float g_h2b[BN * TT];         // layer2 bwd output (time-indexed)
__device__ int   g_clf[BN];              // fwd convergence clamp per batch
__device__ int   g_clb[BN];              // bwd convergence clamp per batch

__device__ __forceinline__ float sigx(float x) {
    return __fdividef(1.0f, 1.0f + __expf(-x));
}
__device__ __forceinline__ float tanhx(float x) {
    return __fdividef(2.0f, 1.0f + __expf(-2.0f * x)) - 1.0f;
}

// ---------------------------------------------------------------------------
// Kernel A: xg1[dir][b][g] = (b_ih+b_hh)[g] + sum_e W_ih[g][e] * x[b][e]
// Input is constant in time -> computed ONCE per (b, dir).
// ---------------------------------------------------------------------------
__global__ void __launch_bounds__(256) xg1_kernel(
    const float* __restrict__ x,
    const float* __restrict__ Wif, const float* __restrict__ bif, const float* __restrict__ bhf,
    const float* __restrict__ Wib, const float* __restrict__ bib, const float* __restrict__ bhb)
{
    __shared__ __align__(16) float sx[EE];
    int b = blockIdx.x;
    int tid = threadIdx.x;
    if (tid < EE) sx[tid] = x[b * EE + tid];
    __syncthreads();

    for (int o = tid; o < 2 * G1N; o += 256) {
        int dir = o / G1N;
        int g = o - dir * G1N;
        const float* W = dir ? Wib : Wif;
        float acc = dir ? (bib[g] + bhb[g]) : (bif[g] + bhf[g]);
        const float4* wr = (const float4*)&W[g * EE];
        #pragma unroll
        for (int e = 0; e < EE / 4; e++) {
            float4 w = wr[e];
            float4 xv = *(const float4*)&sx[4 * e];
            acc += w.x * xv.x + w.y * xv.y + w.z * xv.z + w.w * xv.w;
        }
        g_xg1[dir * BN * G1N + b * G1N + g] = acc;
    }
}

// ---------------------------------------------------------------------------
// Kernel B: layer-1 recurrence, 8 batch lanes per CTA (was 4 in the measured
// 1030us version; structure otherwise identical). Gate thread g (0..199)
// holds its W_hh row in registers and accumulates 8 lanes per step
// (400 FFMA + 100 LDS.128 between barriers -> barrier overhead per batch
// element halved, which the measured ~50% issue efficiency attributed to).
// Update phase: 200 threads x 2 (unit,lane) pairs (addr = tid and tid+200,
// bank-conflict-free). Bitwise fixed-point early exit via __syncthreads_and.
// ---------------------------------------------------------------------------
__global__ void __launch_bounds__(256, 2) lstm1_kernel(
    const float* __restrict__ Whhf, const float* __restrict__ Whhb)
{
    int grp = blockIdx.x;      // 0..127  (batch group of 8)
    int dir = blockIdx.y;      // 0..1
    int b0 = grp * 8;
    const float* Whh = dir ? Whhb : Whhf;
    float* hout = dir ? g_hb : g_hf;
    int* clampp = dir ? g_clb : g_clf;

    __shared__ __align__(16) float sh_h[H1N * 8];   // h[j][lane]
    __shared__ __align__(16) float sh_g[G1N * 8];   // gates[g][lane]

    int tid = threadIdx.x;
    float W[H1N];
    float xg[8];
    if (tid < G1N) {
        #pragma unroll
        for (int j = 0; j < H1N; j++) W[j] = Whh[tid * H1N + j];
        const float* xb = g_xg1 + dir * BN * G1N;
        #pragma unroll
        for (int l = 0; l < 8; l++) xg[l] = xb[(b0 + l) * G1N + tid];
    }
    for (int i = tid; i < H1N * 8; i += 256) sh_h[i] = 0.f;

    // update-phase mapping: pair0 = tid, pair1 = tid + 200 (for tid < 200)
    int u0 = tid >> 3, l0 = tid & 7;
    int u1 = (tid + 200) >> 3, l1 = (tid + 200) & 7;
    float c0 = 0.f, h0 = 0.f, c1 = 0.f, h1 = 0.f;
    bool is_tanh = (tid >= 2 * H1N) && (tid < 3 * H1N);   // g-gate rows
    __syncthreads();

    int tconv = TT - 1;
    for (int t = 0; t < TT; t++) {
        if (tid < G1N) {
            float a[8];
            #pragma unroll
            for (int l = 0; l < 8; l++) a[l] = xg[l];
            #pragma unroll
            for (int j = 0; j < H1N; j++) {
                float4 hva = *(const float4*)&sh_h[j * 8];
                float4 hvb = *(const float4*)&sh_h[j * 8 + 4];
                float w = W[j];
                a[0] += w * hva.x; a[1] += w * hva.y;
                a[2] += w * hva.z; a[3] += w * hva.w;
                a[4] += w * hvb.x; a[5] += w * hvb.y;
                a[6] += w * hvb.z; a[7] += w * hvb.w;
            }
            if (is_tanh) {
                #pragma unroll
                for (int l = 0; l < 8; l++) a[l] = tanhx(a[l]);
            } else {
                #pragma unroll
                for (int l = 0; l < 8; l++) a[l] = sigx(a[l]);
            }
            *(float4*)&sh_g[tid * 8]     = make_float4(a[0], a[1], a[2], a[3]);
            *(float4*)&sh_g[tid * 8 + 4] = make_float4(a[4], a[5], a[6], a[7]);
        }
        __syncthreads();
        int pred = 1;
        if (tid < G1N) {
            // pair 0: addresses (gate*50+u0)*8 + l0 ; for i-gate this is tid
            {
                float iv = sh_g[(u0) * 8 + l0];
                float fv = sh_g[(H1N + u0) * 8 + l0];
                float gv = sh_g[(2 * H1N + u0) * 8 + l0];
                float ov = sh_g[(3 * H1N + u0) * 8 + l0];
                float cn = fv * c0 + iv * gv;
                float hn = ov * tanhx(cn);
                pred &= (__float_as_int(cn) == __float_as_int(c0)) &
                        (__float_as_int(hn) == __float_as_int(h0));
                c0 = cn; h0 = hn;
                sh_h[u0 * 8 + l0] = hn;
                hout[((b0 + l0) * TT + t) * HS + u0] = hn;
            }
            // pair 1
            {
                float iv = sh_g[(u1) * 8 + l1];
                float fv = sh_g[(H1N + u1) * 8 + l1];
                float gv = sh_g[(2 * H1N + u1) * 8 + l1];
                float ov = sh_g[(3 * H1N + u1) * 8 + l1];
                float cn = fv * c1 + iv * gv;
                float hn = ov * tanhx(cn);
                pred &= (__float_as_int(cn) == __float_as_int(c1)) &
                        (__float_as_int(hn) == __float_as_int(h1));
                c1 = cn; h1 = hn;
                sh_h[u1 * 8 + l1] = hn;
                hout[((b0 + l1) * TT + t) * HS + u1] = hn;
            }
        }
        int conv = __syncthreads_and(pred);
        if (conv) { tconv = t; break; }   // state repeated bitwise -> exact from here on
    }
    if (tid < 8) clampp[b0 + tid] = tconv;
}

// ---------------------------------------------------------------------------
// Kernel C: layer-2 input gates. One thread per (b, t).
//   h1[b][t] = [hf[b][t], hb_dir[b][511-t]]   (clamped by convergence index)
//   xg2f[b][t]      = b2f + W_ih2f . h1[b][t]
//   xg2b[b][511-t]  = b2b + W_ih2b . h1[b][t]
// ---------------------------------------------------------------------------
__global__ void __launch_bounds__(256) xg2_kernel(
    const float* __restrict__ Wf, const float* __restrict__ Wb,
    const float* __restrict__ bif, const float* __restrict__ bhf,
    const float* __restrict__ bib, const float* __restrict__ bhb)
{
    __shared__ __align__(16) float sWf[4 * 104];
    __shared__ __align__(16) float sWb[4 * 104];
    __shared__ float sbf[4], sbb[4];
    int tid = threadIdx.x;
    for (int i = tid; i < 400; i += 256) {
        int g = i / 100, j = i - g * 100;
        int off = g * 104 + j + (j >= 50 ? 2 : 0);  // hb half padded to 16B align
        sWf[off] = Wf[i];
        sWb[off] = Wb[i];
    }
    if (tid < 4) { sbf[tid] = bif[tid] + bhf[tid]; sbb[tid] = bib[tid] + bhb[tid]; }
    __syncthreads();

    int idx = blockIdx.x * 256 + tid;
    int b = idx >> 9;
    int t = idx & (TT - 1);
    int tc = min(t, g_clf[b]);
    int sc = min(TT - 1 - t, g_clb[b]);
    const float* hfr = &g_hf[(b * TT + tc) * HS];
    const float* hbr = &g_hb[(b * TT + sc) * HS];

    float accf[4], accb[4];
    #pragma unroll
    for (int g = 0; g < 4; g++) { accf[g] = sbf[g]; accb[g] = sbb[g]; }

    // forward-h half (weight cols 0..49)
    #pragma unroll
    for (int k = 0; k < 12; k++) {
        float4 hv = *(const float4*)&hfr[4 * k];
        #pragma unroll
        for (int g = 0; g < 4; g++) {
            float4 wf = *(const float4*)&sWf[g * 104 + 4 * k];
            float4 wb = *(const float4*)&sWb[g * 104 + 4 * k];
            accf[g] += wf.x * hv.x + wf.y * hv.y + wf.z * hv.z + wf.w * hv.w;
            accb[g] += wb.x * hv.x + wb.y * hv.y + wb.z * hv.z + wb.w * hv.w;
        }
    }
    {
        float h48 = hfr[48], h49 = hfr[49];
        #pragma unroll
        for (int g = 0; g < 4; g++) {
            accf[g] += sWf[g * 104 + 48] * h48 + sWf[g * 104 + 49] * h49;
            accb[g] += sWb[g * 104 + 48] * h48 + sWb[g * 104 + 49] * h49;
        }
    }
    // backward-h half (weight cols 50..99, stored at smem offset 52..101)
    #pragma unroll
    for (int k = 0; k < 12; k++) {
        float4 hv = *(const float4*)&hbr[4 * k];
        #pragma unroll
        for (int g = 0; g < 4; g++) {
            float4 wf = *(const float4*)&sWf[g * 104 + 52 + 4 * k];
            float4 wb = *(const float4*)&sWb[g * 104 + 52 + 4 * k];
            accf[g] += wf.x * hv.x + wf.y * hv.y + wf.z * hv.z + wf.w * hv.w;
            accb[g] += wb.x * hv.x + wb.y * hv.y + wb.z * hv.z + wb.w * hv.w;
        }
    }
    {
        float h48 = hbr[48], h49 = hbr[49];
        #pragma unroll
        for (int g = 0; g < 4; g++) {
            accf[g] += sWf[g * 104 + 100] * h48 + sWf[g * 104 + 101] * h49;
            accb[g] += sWb[g * 104 + 100] * h48 + sWb[g * 104 + 101] * h49;
        }
    }

    *(float4*)&g_xg2f[(b * TT + t) * 4] = make_float4(accf[0], accf[1], accf[2], accf[3]);
    *(float4*)&g_xg2b[(b * TT + (TT - 1 - t)) * 4] = make_float4(accb[0], accb[1], accb[2], accb[3]);
}

// ---------------------------------------------------------------------------
// Kernel D: layer-2 recurrence, quad-gate layout (measured 182us) + depth-4
// register prefetch ring. The per-step gate-input load was measured to
// dominate the dependent chain (~700 cyc/step at occ 2.6%); prefetching
// pre[t+4] each iteration gives ~4 chain-lengths (~600 cyc) of cover, taking
// the L2/DRAM latency off the serial path.
// ---------------------------------------------------------------------------
__global__ void __launch_bounds__(32) lstm2_kernel(
    const float* __restrict__ Whhf, const float* __restrict__ Whhb,
    float* __restrict__ out)
{
    int gid = blockIdx.x * 32 + threadIdx.x;   // 0..8191
    int chain = gid >> 2;                       // 0..2047
    int gt = gid & 3;
    int b = chain & (BN - 1);
    bool bwd = (chain >= BN);
    const float* Whh = bwd ? Whhb : Whhf;
    float w = Whh[gt];
    const float* pre = (bwd ? g_xg2b : g_xg2f) + b * TT * 4 + gt;
    bool is_tanh = (gt == 2);
    bool is_st = (gt == 0);
    int qb = (threadIdx.x & 31) & ~3;

    // depth-4 prefetch ring
    float buf[4];
    #pragma unroll
    for (int k = 0; k < 4; k++) buf[k] = pre[k * 4];
    const float* pf = pre + 16;   // points at step t+4 gate input

    float h = 0.f, c = 0.f;
    for (int t = 0; t < TT; t++) {
        float p = buf[t & 3];
        if (t < TT - 4) buf[t & 3] = pf[0];   // prefetch step t+4 (off the chain)
        pf += 4;

        float a = p + w * h;
        a = is_tanh ? tanhx(a) : sigx(a);
        float xi = __shfl_sync(0xFFFFFFFFu, a, qb + 0);
        float xf = __shfl_sync(0xFFFFFFFFu, a, qb + 1);
        float xgg = __shfl_sync(0xFFFFFFFFu, a, qb + 2);
        float xo = __shfl_sync(0xFFFFFFFFu, a, qb + 3);
        c = xf * c + xi * xgg;
        h = xo * tanhx(c);
        if (is_st) {
            if (!bwd) out[b * TT + t] = h;
            else      g_h2b[b * TT + (TT - 1 - t)] = h;
        }
    }
}

// ---------------------------------------------------------------------------
// Kernel E: out += h2b (final channel sum)
// ---------------------------------------------------------------------------
__global__ void __launch_bounds__(256) addout_kernel(float* __restrict__ out)
{
    int i = blockIdx.x * 256 + threadIdx.x;   // 0..131071 float4s
    float4* o = (float4*)out;
    const float4* s = (const float4*)g_h2b;
    float4 a = o[i], bv = s[i];
    a.x += bv.x; a.y += bv.y; a.z += bv.z; a.w += bv.w;
    o[i] = a;
}

// ---------------------------------------------------------------------------
extern "C" void kernel_launch(void* const* d_in, const int* in_sizes, int n_in,
                              void* d_out, int out_size)
{
    const float* x    = (const float*)d_in[0];
    const float* Wif1 = (const float*)d_in[1];
    const float* Whf1 = (const float*)d_in[2];
    const float* bif1 = (const float*)d_in[3];
    const float* bhf1 = (const float*)d_in[4];
    const float* Wib1 = (const float*)d_in[5];
    const float* Whb1 = (const float*)d_in[6];
    const float* bib1 = (const float*)d_in[7];
    const float* bhb1 = (const float*)d_in[8];
    const float* Wif2 = (const float*)d_in[9];
    const float* Whf2 = (const float*)d_in[10];
    const float* bif2 = (const float*)d_in[11];
    const float* bhf2 = (const float*)d_in[12];
    const float* Wib2 = (const float*)d_in[13];
    const float* Whb2 = (const float*)d_in[14];
    const float* bib2 = (const float*)d_in[15];
    const float* bhb2 = (const float*)d_in[16];
    float* out = (float*)d_out;

    xg1_kernel<<<BN, 256>>>(x, Wif1, bif1, bhf1, Wib1, bib1, bhb1);
    dim3 gB(BN / 8, 2);
    lstm1_kernel<<<gB, 256>>>(Whf1, Whb1);
    xg2_kernel<<<(BN * TT) / 256, 256>>>(Wif2, Wib2, bif2, bhf2, bib2, bhb2);
    lstm2_kernel<<<256, 32>>>(Whf2, Whb2, out);
    addout_kernel<<<(BN * TT) / 1024, 256>>>(out);
}